// round 5
// baseline (speedup 1.0000x reference)
#include <cuda_runtime.h>

// PrimitiveGate: apply complex 2x2 gate to qubit axis 12 of a 23-qubit state,
// batch 4. State layout: (DIM, BATCH) float32, re and im planes separate.
// Output: (2, DIM, BATCH) float32 -> [out_re | out_im].
//
// Axis 12 of 23 (axis 0 = MSB) -> bit 10 of the dim index.
// BATCH=4 contiguous floats per dim index -> one float4 per (dim, batch-row).
//
// HBM-roofline kernel: 536 MB irreducible traffic at ~6.5 TB/s (82% of spec,
// the B300 mixed-R/W streaming ceiling). Session evidence:
//   R2: .cs hints        -> neutral   (L2 policy not the limiter)
//   R3: ILP=2/MLP=8      -> regressed (occ 80->63%, DRAM -2.6%)
//   R4: re-bench         -> reproduced; spread is DRAM noise
// R5: block 256 -> 512 (halve CTA count / scheduling events; identical
// memory pattern). Expected neutral; final-floor confirmation.

#define N_QUBITS 23
#define TARGET_BIT 10            // N_QUBITS - 1 - TARGET_Q(12)
#define DIM (1u << N_QUBITS)     // 8388608
#define NPAIRS (DIM >> 1)        // 4194304
#define LOWMASK ((1u << TARGET_BIT) - 1u)
#define TPB 512

__global__ void __launch_bounds__(TPB)
gate_kernel(const float4* __restrict__ sre,
            const float4* __restrict__ sim,
            const float*  __restrict__ mre,
            const float*  __restrict__ mim,
            float4* __restrict__ out)
{
    unsigned p = blockIdx.x * (unsigned)TPB + threadIdx.x;

    // i0: insert a 0 at bit TARGET_BIT; i1 = i0 | (1<<TARGET_BIT)
    unsigned i0 = ((p & ~LOWMASK) << 1) | (p & LOWMASK);
    unsigned i1 = i0 | (1u << TARGET_BIT);

    // Front-batched independent streaming loads (MLP = 4), evict-first
    float4 a_re = __ldcs(&sre[i0]);
    float4 b_re = __ldcs(&sre[i1]);
    float4 a_im = __ldcs(&sim[i0]);
    float4 b_im = __ldcs(&sim[i1]);

    // 2x2 complex gate, row-major (tiny, hot in L1 — normal loads)
    float m00r = __ldg(&mre[0]), m01r = __ldg(&mre[1]);
    float m10r = __ldg(&mre[2]), m11r = __ldg(&mre[3]);
    float m00i = __ldg(&mim[0]), m01i = __ldg(&mim[1]);
    float m10i = __ldg(&mim[2]), m11i = __ldg(&mim[3]);

    float4 o0r, o0i, o1r, o1i;

#define LANE(f)                                                                 \
    do {                                                                        \
        float s0r = a_re.f, s0i = a_im.f, s1r = b_re.f, s1i = b_im.f;           \
        o0r.f = fmaf(m00r, s0r, fmaf(-m00i, s0i, fmaf(m01r, s1r, -m01i * s1i)));\
        o0i.f = fmaf(m00r, s0i, fmaf( m00i, s0r, fmaf(m01r, s1i,  m01i * s1r)));\
        o1r.f = fmaf(m10r, s0r, fmaf(-m10i, s0i, fmaf(m11r, s1r, -m11i * s1i)));\
        o1i.f = fmaf(m10r, s0i, fmaf( m10i, s0r, fmaf(m11r, s1i,  m11i * s1r)));\
    } while (0)

    LANE(x); LANE(y); LANE(z); LANE(w);
#undef LANE

    // out_re plane at [0, DIM), out_im plane at [DIM, 2*DIM) (in float4 units)
    // Streaming stores: full-line coalesced, evict-first.
    __stcs(&out[i0],       o0r);
    __stcs(&out[i1],       o1r);
    __stcs(&out[DIM + i0], o0i);
    __stcs(&out[DIM + i1], o1i);
}

extern "C" void kernel_launch(void* const* d_in, const int* in_sizes, int n_in,
                              void* d_out, int out_size)
{
    const float4* sre = (const float4*)d_in[0];
    const float4* sim = (const float4*)d_in[1];
    const float*  mre = (const float*)d_in[2];
    const float*  mim = (const float*)d_in[3];
    float4* out = (float4*)d_out;

    dim3 grid(NPAIRS / TPB);  // 8192 blocks, exact
    gate_kernel<<<grid, TPB>>>(sre, sim, mre, mim, out);
}

// round 6
// speedup vs baseline: 1.0035x; 1.0035x over previous
#include <cuda_runtime.h>

// PrimitiveGate: apply complex 2x2 gate to qubit axis 12 of a 23-qubit state,
// batch 4. State layout: (DIM, BATCH) float32, re and im planes separate.
// Output: (2, DIM, BATCH) float32 -> [out_re | out_im].
//
// Axis 12 of 23 (axis 0 = MSB) -> bit 10 of the dim index.
// BATCH=4 contiguous floats per dim index -> one float4 per (dim, batch-row).
//
// FINAL. HBM-roofline kernel: 536 MB irreducible traffic at ~6.5 TB/s
// (~82% of 8 TB/s spec = the B300 mixed-R/W streaming ceiling; the residual
// is DRAM bus-turnaround/refresh, not SM-addressable). Session evidence:
//   R2: .cs streaming hints  -> neutral   (L2 policy not the limiter)
//   R3: ILP=2 / MLP=8        -> regressed (occ 80->63%, DRAM -2.6%)
//   R4: re-bench             -> reproduced (noise +-1%)
//   R5: block 256->512       -> neutral   (scheduling not the limiter)
// One pair per thread, 32 regs, ~80% occ, exact float4 coalescing.

#define N_QUBITS 23
#define TARGET_BIT 10            // N_QUBITS - 1 - TARGET_Q(12)
#define DIM (1u << N_QUBITS)     // 8388608
#define NPAIRS (DIM >> 1)        // 4194304
#define LOWMASK ((1u << TARGET_BIT) - 1u)

__global__ void __launch_bounds__(256)
gate_kernel(const float4* __restrict__ sre,
            const float4* __restrict__ sim,
            const float*  __restrict__ mre,
            const float*  __restrict__ mim,
            float4* __restrict__ out)
{
    unsigned p = blockIdx.x * 256u + threadIdx.x;

    // i0: insert a 0 at bit TARGET_BIT; i1 = i0 | (1<<TARGET_BIT)
    unsigned i0 = ((p & ~LOWMASK) << 1) | (p & LOWMASK);
    unsigned i1 = i0 | (1u << TARGET_BIT);

    // Front-batched independent streaming loads (MLP = 4), evict-first
    float4 a_re = __ldcs(&sre[i0]);
    float4 b_re = __ldcs(&sre[i1]);
    float4 a_im = __ldcs(&sim[i0]);
    float4 b_im = __ldcs(&sim[i1]);

    // 2x2 complex gate, row-major (tiny, hot in L1 — normal loads)
    float m00r = __ldg(&mre[0]), m01r = __ldg(&mre[1]);
    float m10r = __ldg(&mre[2]), m11r = __ldg(&mre[3]);
    float m00i = __ldg(&mim[0]), m01i = __ldg(&mim[1]);
    float m10i = __ldg(&mim[2]), m11i = __ldg(&mim[3]);

    float4 o0r, o0i, o1r, o1i;

#define LANE(f)                                                                 \
    do {                                                                        \
        float s0r = a_re.f, s0i = a_im.f, s1r = b_re.f, s1i = b_im.f;           \
        o0r.f = fmaf(m00r, s0r, fmaf(-m00i, s0i, fmaf(m01r, s1r, -m01i * s1i)));\
        o0i.f = fmaf(m00r, s0i, fmaf( m00i, s0r, fmaf(m01r, s1i,  m01i * s1r)));\
        o1r.f = fmaf(m10r, s0r, fmaf(-m10i, s0i, fmaf(m11r, s1r, -m11i * s1i)));\
        o1i.f = fmaf(m10r, s0i, fmaf( m10i, s0r, fmaf(m11r, s1i,  m11i * s1r)));\
    } while (0)

    LANE(x); LANE(y); LANE(z); LANE(w);
#undef LANE

    // out_re plane at [0, DIM), out_im plane at [DIM, 2*DIM) (in float4 units)
    // Streaming stores: full-line coalesced, evict-first.
    __stcs(&out[i0],       o0r);
    __stcs(&out[i1],       o1r);
    __stcs(&out[DIM + i0], o0i);
    __stcs(&out[DIM + i1], o1i);
}

extern "C" void kernel_launch(void* const* d_in, const int* in_sizes, int n_in,
                              void* d_out, int out_size)
{
    const float4* sre = (const float4*)d_in[0];
    const float4* sim = (const float4*)d_in[1];
    const float*  mre = (const float*)d_in[2];
    const float*  mim = (const float*)d_in[3];
    float4* out = (float4*)d_out;

    dim3 grid(NPAIRS / 256);  // 16384 blocks, exact
    gate_kernel<<<grid, 256>>>(sre, sim, mre, mim, out);
}

// round 7
// speedup vs baseline: 1.0039x; 1.0004x over previous
#include <cuda_runtime.h>

// PrimitiveGate: apply complex 2x2 gate to qubit axis 12 of a 23-qubit state,
// batch 4. State layout: (DIM, BATCH) float32, re and im planes separate.
// Output: (2, DIM, BATCH) float32 -> [out_re | out_im].
//
// Axis 12 of 23 (axis 0 = MSB) -> bit 10 of the dim index.
// BATCH=4 contiguous floats per dim index -> one float4 per (dim, batch-row).
//
// FINAL — committed at the HBM roofline. 536 MB irreducible traffic at
// ~6.5 TB/s (~82% of 8 TB/s spec = the B300 mixed-R/W streaming ceiling;
// the residual is DRAM bus-turnaround/refresh, not SM-addressable).
// Session evidence (6 rounds):
//   R2: .cs streaming hints  -> neutral   (L2 policy not the limiter)
//   R3: ILP=2 / MLP=8        -> regressed (occ 80->63%, DRAM -2.6%)
//   R4: re-bench             -> reproduced (noise +-1%)
//   R5: block 256->512       -> neutral   (scheduling not the limiter)
//   R6: re-bench             -> reproduced; floor confirmed 3x
// One pair per thread, 32 regs, ~80% occ, exact float4 coalescing,
// 100% sector efficiency, issue=17% (SMs idle on DRAM as expected).

#define N_QUBITS 23
#define TARGET_BIT 10            // N_QUBITS - 1 - TARGET_Q(12)
#define DIM (1u << N_QUBITS)     // 8388608
#define NPAIRS (DIM >> 1)        // 4194304
#define LOWMASK ((1u << TARGET_BIT) - 1u)

__global__ void __launch_bounds__(256)
gate_kernel(const float4* __restrict__ sre,
            const float4* __restrict__ sim,
            const float*  __restrict__ mre,
            const float*  __restrict__ mim,
            float4* __restrict__ out)
{
    unsigned p = blockIdx.x * 256u + threadIdx.x;

    // i0: insert a 0 at bit TARGET_BIT; i1 = i0 | (1<<TARGET_BIT)
    unsigned i0 = ((p & ~LOWMASK) << 1) | (p & LOWMASK);
    unsigned i1 = i0 | (1u << TARGET_BIT);

    // Front-batched independent streaming loads (MLP = 4), evict-first
    float4 a_re = __ldcs(&sre[i0]);
    float4 b_re = __ldcs(&sre[i1]);
    float4 a_im = __ldcs(&sim[i0]);
    float4 b_im = __ldcs(&sim[i1]);

    // 2x2 complex gate, row-major (tiny, hot in L1 — normal loads)
    float m00r = __ldg(&mre[0]), m01r = __ldg(&mre[1]);
    float m10r = __ldg(&mre[2]), m11r = __ldg(&mre[3]);
    float m00i = __ldg(&mim[0]), m01i = __ldg(&mim[1]);
    float m10i = __ldg(&mim[2]), m11i = __ldg(&mim[3]);

    float4 o0r, o0i, o1r, o1i;

#define LANE(f)                                                                 \
    do {                                                                        \
        float s0r = a_re.f, s0i = a_im.f, s1r = b_re.f, s1i = b_im.f;           \
        o0r.f = fmaf(m00r, s0r, fmaf(-m00i, s0i, fmaf(m01r, s1r, -m01i * s1i)));\
        o0i.f = fmaf(m00r, s0i, fmaf( m00i, s0r, fmaf(m01r, s1i,  m01i * s1r)));\
        o1r.f = fmaf(m10r, s0r, fmaf(-m10i, s0i, fmaf(m11r, s1r, -m11i * s1i)));\
        o1i.f = fmaf(m10r, s0i, fmaf( m10i, s0r, fmaf(m11r, s1i,  m11i * s1r)));\
    } while (0)

    LANE(x); LANE(y); LANE(z); LANE(w);
#undef LANE

    // out_re plane at [0, DIM), out_im plane at [DIM, 2*DIM) (in float4 units)
    // Streaming stores: full-line coalesced, evict-first.
    __stcs(&out[i0],       o0r);
    __stcs(&out[i1],       o1r);
    __stcs(&out[DIM + i0], o0i);
    __stcs(&out[DIM + i1], o1i);
}

extern "C" void kernel_launch(void* const* d_in, const int* in_sizes, int n_in,
                              void* d_out, int out_size)
{
    const float4* sre = (const float4*)d_in[0];
    const float4* sim = (const float4*)d_in[1];
    const float*  mre = (const float*)d_in[2];
    const float*  mim = (const float*)d_in[3];
    float4* out = (float4*)d_out;

    dim3 grid(NPAIRS / 256);  // 16384 blocks, exact
    gate_kernel<<<grid, 256>>>(sre, sim, mre, mim, out);
}